// round 2
// baseline (speedup 1.0000x reference)
#include <cuda_runtime.h>

#define Bsz 8
#define Lsz 1024
#define Dsz 512
#define HDsz 64
#define NCsz 128
#define Msz (Bsz*Lsz)
#define OUTHALF ((size_t)Msz*Dsz)
#define NEG_INF (-__int_as_float(0x7f800000))

__device__ float g_zr[Msz*Dsz];
__device__ float g_qr[Msz*Dsz], g_qi[Msz*Dsz];
__device__ float g_kr[Msz*Dsz], g_ki[Msz*Dsz];
__device__ float g_vr[Msz*Dsz], g_vi[Msz*Dsz];
__device__ float g_ar[Msz*Dsz], g_ai[Msz*Dsz];
__device__ float g_pr[Msz*Dsz], g_pi[Msz*Dsz];
__device__ int   g_idx[Msz];
__device__ float g_stk[Msz*Dsz];
__device__ float g_cn2[NCsz], g_gp[NCsz], g_go[NCsz];
__device__ double g_loss;

// ---------- prep: code norms, gate tables, loss reset ----------
__global__ void prep_kernel(const float* __restrict__ cb,
                            const float* __restrict__ gw,
                            const float* __restrict__ gb) {
    int j = threadIdx.x;
    if (j == 0) g_loss = 0.0;
    if (j < NCsz) {
        float s2 = 0.f, d0 = 0.f, d1 = 0.f;
        for (int d = 0; d < Dsz; d++) {
            float c = cb[j*Dsz + d];
            s2 += c*c; d0 += c*gw[d*2+0]; d1 += c*gw[d*2+1];
        }
        g_cn2[j] = s2;
        g_gp[j] = 1.f/(1.f+expf(-(d0+gb[0])));
        g_go[j] = 1.f/(1.f+expf(-(d1+gb[1])));
    }
}

// ---------- embedding gather ----------
__global__ void gather_kernel(const int* __restrict__ tokens,
                              const float* __restrict__ embed) {
    int m = blockIdx.x;
    const float4* src = (const float4*)(embed + (size_t)tokens[m]*Dsz);
    ((float4*)(g_zr + (size_t)m*Dsz))[threadIdx.x] = src[threadIdx.x];
}

// ---------- 6-way projection GEMM ----------
__global__ __launch_bounds__(256) void proj_kernel(
        const float* __restrict__ qw, const float* __restrict__ qb,
        const float* __restrict__ kw, const float* __restrict__ kb,
        const float* __restrict__ vw, const float* __restrict__ vb) {
    __shared__ float As[8][128], Bs[8][128];
    const int z = blockIdx.z, pair = z>>1, im = z&1;
    const float* W; const float* bias; float* C;
    if (pair==0){W=qw;bias=qb;C=im?g_qi:g_qr;}
    else if (pair==1){W=kw;bias=kb;C=im?g_ki:g_kr;}
    else {W=vw;bias=vb;C=im?g_vi:g_vr;}
    W += (size_t)im*Dsz*Dsz;
    const float sgn = im?1.f:-1.f;
    const int m0=blockIdx.y*128, n0=blockIdx.x*128;
    const int tid=threadIdx.x, ty=tid>>4, tx=tid&15;
    const int arow=tid>>1, akg=(tid&1)*4;
    const int brow=tid>>5, bcol=(tid&31)*4;
    float acc[8][8];
#pragma unroll
    for(int i=0;i<8;i++)
#pragma unroll
        for(int j=0;j<8;j++) acc[i][j]=0.f;
    for(int k0=0;k0<Dsz;k0+=8){
        float4 av=*(const float4*)(g_zr+(size_t)(m0+arow)*Dsz+k0+akg);
        float4 bv=*(const float4*)(W+(size_t)(k0+brow)*Dsz+n0+bcol);
        __syncthreads();
        As[akg+0][arow]=av.x;As[akg+1][arow]=av.y;As[akg+2][arow]=av.z;As[akg+3][arow]=av.w;
        *(float4*)&Bs[brow][bcol]=bv;
        __syncthreads();
#pragma unroll
        for(int kk=0;kk<8;kk++){
            float4 a0=*(float4*)&As[kk][ty*8],a1=*(float4*)&As[kk][ty*8+4];
            float4 b0=*(float4*)&Bs[kk][tx*8],b1=*(float4*)&Bs[kk][tx*8+4];
            float a[8]={a0.x,a0.y,a0.z,a0.w,a1.x,a1.y,a1.z,a1.w};
            float b[8]={b0.x,b0.y,b0.z,b0.w,b1.x,b1.y,b1.z,b1.w};
#pragma unroll
            for(int i=0;i<8;i++)
#pragma unroll
                for(int j=0;j<8;j++) acc[i][j]+=a[i]*b[j];
        }
    }
    float bv_[8];
#pragma unroll
    for(int j=0;j<8;j++){int n=n0+tx*8+j; bv_[j]=bias[n]+sgn*bias[Dsz+n];}
#pragma unroll
    for(int i=0;i<8;i++){
        float* cr=C+(size_t)(m0+ty*8+i)*Dsz+n0+tx*8;
        *(float4*)(cr)  =make_float4(acc[i][0]+bv_[0],acc[i][1]+bv_[1],acc[i][2]+bv_[2],acc[i][3]+bv_[3]);
        *(float4*)(cr+4)=make_float4(acc[i][4]+bv_[4],acc[i][5]+bv_[5],acc[i][6]+bv_[6],acc[i][7]+bv_[7]);
    }
}

// ---------- flash attention (complex scores, dual V) ----------
#define AP 68
__global__ __launch_bounds__(256) void attn_kernel() {
    extern __shared__ float sm[];
    float* sQr=sm;            float* sQi=sQr+64*AP;
    float* sKr=sQi+64*AP;     float* sKi=sKr+64*AP;
    float* sVr=sKi+64*AP;     float* sVi=sVr+64*AP;
    float* sP =sVi+64*AP;
    const int bh=blockIdx.y, b=bh>>3, h=bh&7;
    const int i0=blockIdx.x*64;
    const int tid=threadIdx.x, ty=tid>>4, tx=tid&15;
    const size_t base=(size_t)b*Lsz*Dsz + h*HDsz;
#pragma unroll
    for(int u=0;u<4;u++){
        int li=tid+u*256, r=li>>4, c4=(li&15)*4;
        size_t g=base+(size_t)(i0+r)*Dsz+c4;
        *(float4*)&sQr[r*AP+c4]=*(const float4*)(g_qr+g);
        *(float4*)&sQi[r*AP+c4]=*(const float4*)(g_qi+g);
    }
    float m_run[4],l_run[4],accr[4][4],acci[4][4];
#pragma unroll
    for(int i=0;i<4;i++){m_run[i]=NEG_INF;l_run[i]=0.f;
#pragma unroll
        for(int j=0;j<4;j++){accr[i][j]=0.f;acci[i][j]=0.f;}}
    for(int jt=0;jt<=blockIdx.x;jt++){
        const int s0=jt*64;
        __syncthreads();
#pragma unroll
        for(int u=0;u<4;u++){
            int li=tid+u*256, r=li>>4, c4=(li&15)*4;
            size_t g=base+(size_t)(s0+r)*Dsz+c4;
            float4 a=*(const float4*)(g_kr+g);
            float4 c=*(const float4*)(g_ki+g);
            sKr[(c4+0)*AP+r]=a.x;sKr[(c4+1)*AP+r]=a.y;sKr[(c4+2)*AP+r]=a.z;sKr[(c4+3)*AP+r]=a.w;
            sKi[(c4+0)*AP+r]=c.x;sKi[(c4+1)*AP+r]=c.y;sKi[(c4+2)*AP+r]=c.z;sKi[(c4+3)*AP+r]=c.w;
            *(float4*)&sVr[r*AP+c4]=*(const float4*)(g_vr+g);
            *(float4*)&sVi[r*AP+c4]=*(const float4*)(g_vi+g);
        }
        __syncthreads();
        float s_[4][4];
#pragma unroll
        for(int i=0;i<4;i++)
#pragma unroll
            for(int j=0;j<4;j++) s_[i][j]=0.f;
#pragma unroll
        for(int k4=0;k4<16;k4++){
            float qrv[4][4],qiv[4][4];
#pragma unroll
            for(int i=0;i<4;i++){
                float4 t=*(float4*)&sQr[(4*ty+i)*AP+4*k4];
                qrv[i][0]=t.x;qrv[i][1]=t.y;qrv[i][2]=t.z;qrv[i][3]=t.w;
                float4 u=*(float4*)&sQi[(4*ty+i)*AP+4*k4];
                qiv[i][0]=u.x;qiv[i][1]=u.y;qiv[i][2]=u.z;qiv[i][3]=u.w;
            }
#pragma unroll
            for(int kk=0;kk<4;kk++){
                float4 kr4=*(float4*)&sKr[(4*k4+kk)*AP+4*tx];
                float4 ki4=*(float4*)&sKi[(4*k4+kk)*AP+4*tx];
#pragma unroll
                for(int i=0;i<4;i++){
                    s_[i][0]+=qrv[i][kk]*kr4.x+qiv[i][kk]*ki4.x;
                    s_[i][1]+=qrv[i][kk]*kr4.y+qiv[i][kk]*ki4.y;
                    s_[i][2]+=qrv[i][kk]*kr4.z+qiv[i][kk]*ki4.z;
                    s_[i][3]+=qrv[i][kk]*kr4.w+qiv[i][kk]*ki4.w;
                }
            }
        }
        const bool diag=(jt==blockIdx.x);
#pragma unroll
        for(int i=0;i<4;i++)
#pragma unroll
            for(int j=0;j<4;j++){
                s_[i][j]*=0.125f;
                if(diag && (4*tx+j>4*ty+i)) s_[i][j]=NEG_INF;
            }
        float p_[4][4];
#pragma unroll
        for(int i=0;i<4;i++){
            float mx=fmaxf(fmaxf(s_[i][0],s_[i][1]),fmaxf(s_[i][2],s_[i][3]));
#pragma unroll
            for(int off=8;off;off>>=1) mx=fmaxf(mx,__shfl_xor_sync(0xffffffffu,mx,off));
            float mnew=fmaxf(m_run[i],mx);
            float alpha=__expf(m_run[i]-mnew);
            m_run[i]=mnew;
            float rs=0.f;
#pragma unroll
            for(int j=0;j<4;j++){p_[i][j]=__expf(s_[i][j]-mnew);rs+=p_[i][j];}
#pragma unroll
            for(int off=8;off;off>>=1) rs+=__shfl_xor_sync(0xffffffffu,rs,off);
            l_run[i]=l_run[i]*alpha+rs;
#pragma unroll
            for(int j=0;j<4;j++){accr[i][j]*=alpha;acci[i][j]*=alpha;}
        }
#pragma unroll
        for(int i=0;i<4;i++)
            *(float4*)&sP[(4*ty+i)*AP+4*tx]=make_float4(p_[i][0],p_[i][1],p_[i][2],p_[i][3]);
        __syncthreads();
#pragma unroll
        for(int c4=0;c4<16;c4++){
            float pp[4][4];
#pragma unroll
            for(int i=0;i<4;i++){
                float4 t=*(float4*)&sP[(4*ty+i)*AP+4*c4];
                pp[i][0]=t.x;pp[i][1]=t.y;pp[i][2]=t.z;pp[i][3]=t.w;
            }
#pragma unroll
            for(int cc=0;cc<4;cc++){
                float4 vr4=*(float4*)&sVr[(4*c4+cc)*AP+4*tx];
                float4 vi4=*(float4*)&sVi[(4*c4+cc)*AP+4*tx];
#pragma unroll
                for(int i=0;i<4;i++){
                    accr[i][0]+=pp[i][cc]*vr4.x;accr[i][1]+=pp[i][cc]*vr4.y;
                    accr[i][2]+=pp[i][cc]*vr4.z;accr[i][3]+=pp[i][cc]*vr4.w;
                    acci[i][0]+=pp[i][cc]*vi4.x;acci[i][1]+=pp[i][cc]*vi4.y;
                    acci[i][2]+=pp[i][cc]*vi4.z;acci[i][3]+=pp[i][cc]*vi4.w;
                }
            }
        }
    }
#pragma unroll
    for(int i=0;i<4;i++){
        float inv=1.f/l_run[i];
        size_t g=base+(size_t)(i0+4*ty+i)*Dsz+4*tx;
        *(float4*)(g_ar+g)=make_float4(accr[i][0]*inv,accr[i][1]*inv,accr[i][2]*inv,accr[i][3]*inv);
        *(float4*)(g_ai+g)=make_float4(acci[i][0]*inv,acci[i][1]*inv,acci[i][2]*inv,acci[i][3]*inv);
    }
}

// ---------- complex O-projection ----------
__global__ __launch_bounds__(256) void oproj_kernel(const float* __restrict__ ow,
                                                    const float* __restrict__ ob) {
    __shared__ float Ars[8][128],Ais[8][128],B0s[8][64],B1s[8][64];
    const int m0=blockIdx.y*128, n0=blockIdx.x*64;
    const int tid=threadIdx.x, ty=tid>>4, tx=tid&15;
    const int arow=tid>>1, akg=(tid&1)*4;
    const int bkr=(tid&127)>>4, bnn=(tid&15)*4;
    const bool isB1=tid>=128;
    const float* w0=ow; const float* w1=ow+(size_t)Dsz*Dsz;
    float accR[8][4],accI[8][4];
#pragma unroll
    for(int i=0;i<8;i++)
#pragma unroll
        for(int j=0;j<4;j++){accR[i][j]=0.f;accI[i][j]=0.f;}
    for(int k0=0;k0<Dsz;k0+=8){
        float4 av=*(const float4*)(g_ar+(size_t)(m0+arow)*Dsz+k0+akg);
        float4 iv=*(const float4*)(g_ai+(size_t)(m0+arow)*Dsz+k0+akg);
        const float* ws=isB1?w1:w0;
        float4 bv=*(const float4*)(ws+(size_t)(k0+bkr)*Dsz+n0+bnn);
        __syncthreads();
        Ars[akg+0][arow]=av.x;Ars[akg+1][arow]=av.y;Ars[akg+2][arow]=av.z;Ars[akg+3][arow]=av.w;
        Ais[akg+0][arow]=iv.x;Ais[akg+1][arow]=iv.y;Ais[akg+2][arow]=iv.z;Ais[akg+3][arow]=iv.w;
        if(isB1)*(float4*)&B1s[bkr][bnn]=bv; else *(float4*)&B0s[bkr][bnn]=bv;
        __syncthreads();
#pragma unroll
        for(int kk=0;kk<8;kk++){
            float4 a0=*(float4*)&Ars[kk][ty*8],a1=*(float4*)&Ars[kk][ty*8+4];
            float4 c0=*(float4*)&Ais[kk][ty*8],c1=*(float4*)&Ais[kk][ty*8+4];
            float4 b0=*(float4*)&B0s[kk][tx*4],b1=*(float4*)&B1s[kk][tx*4];
            float ar8[8]={a0.x,a0.y,a0.z,a0.w,a1.x,a1.y,a1.z,a1.w};
            float ai8[8]={c0.x,c0.y,c0.z,c0.w,c1.x,c1.y,c1.z,c1.w};
            float bw0[4]={b0.x,b0.y,b0.z,b0.w};
            float bw1[4]={b1.x,b1.y,b1.z,b1.w};
#pragma unroll
            for(int i=0;i<8;i++)
#pragma unroll
                for(int j=0;j<4;j++){
                    accR[i][j]+=ar8[i]*bw0[j]-ai8[i]*bw1[j];
                    accI[i][j]+=ai8[i]*bw0[j]+ar8[i]*bw1[j];
                }
        }
    }
    float bR[4],bI[4];
#pragma unroll
    for(int j=0;j<4;j++){int n=n0+tx*4+j;bR[j]=ob[n]-ob[Dsz+n];bI[j]=ob[n]+ob[Dsz+n];}
#pragma unroll
    for(int i=0;i<8;i++){
        size_t g=(size_t)(m0+ty*8+i)*Dsz+n0+tx*4;
        *(float4*)(g_pr+g)=make_float4(accR[i][0]+bR[0],accR[i][1]+bR[1],accR[i][2]+bR[2],accR[i][3]+bR[3]);
        *(float4*)(g_pi+g)=make_float4(accI[i][0]+bI[0],accI[i][1]+bI[1],accI[i][2]+bI[2],accI[i][3]+bI[3]);
    }
}

// ---------- VQ distance GEMM + first-argmin ----------
__global__ __launch_bounds__(256) void dist_kernel(const float* __restrict__ cb) {
    __shared__ float As[8][128], Bs[8][128];
    __shared__ float2 sRed[128][16];
    const int m0=blockIdx.x*128;
    const int tid=threadIdx.x, ty=tid>>4, tx=tid&15;
    const int arow=tid>>1, akg=(tid&1)*4;
    float acc[8][8];
#pragma unroll
    for(int i=0;i<8;i++)
#pragma unroll
        for(int j=0;j<8;j++) acc[i][j]=0.f;
    for(int k0=0;k0<Dsz;k0+=8){
        float4 av=*(const float4*)(g_pr+(size_t)(m0+arow)*Dsz+k0+akg);
        float4 cv=*(const float4*)(cb+(size_t)arow*Dsz+k0+akg);
        __syncthreads();
        As[akg+0][arow]=av.x;As[akg+1][arow]=av.y;As[akg+2][arow]=av.z;As[akg+3][arow]=av.w;
        Bs[akg+0][arow]=cv.x;Bs[akg+1][arow]=cv.y;Bs[akg+2][arow]=cv.z;Bs[akg+3][arow]=cv.w;
        __syncthreads();
#pragma unroll
        for(int kk=0;kk<8;kk++){
            float4 a0=*(float4*)&As[kk][ty*8],a1=*(float4*)&As[kk][ty*8+4];
            float4 b0=*(float4*)&Bs[kk][tx*8],b1=*(float4*)&Bs[kk][tx*8+4];
            float a[8]={a0.x,a0.y,a0.z,a0.w,a1.x,a1.y,a1.z,a1.w};
            float b[8]={b0.x,b0.y,b0.z,b0.w,b1.x,b1.y,b1.z,b1.w};
#pragma unroll
            for(int i=0;i<8;i++)
#pragma unroll
                for(int j=0;j<8;j++) acc[i][j]+=a[i]*b[j];
        }
    }
#pragma unroll
    for(int i=0;i<8;i++){
        float bd=1e30f; int bi=0;
#pragma unroll
        for(int j=0;j<8;j++){
            int n=tx*8+j;
            float d=g_cn2[n]-2.f*acc[i][j];
            if(d<bd){bd=d;bi=n;}
        }
        sRed[ty*8+i][tx]=make_float2(bd,__int_as_float(bi));
    }
    __syncthreads();
    if(tid<128){
        float bd=1e30f; int bi=0;
#pragma unroll
        for(int t=0;t<16;t++){
            float2 e=sRed[tid][t];
            if(e.x<bd){bd=e.x;bi=__float_as_int(e.y);}
        }
        g_idx[m0+tid]=bi;
    }
}

// ---------- VQ loss (direct) ----------
__global__ void loss_kernel(const float* __restrict__ cb) {
    __shared__ float sw[4];
    int m=blockIdx.x, tid=threadIdx.x;
    const float4 f=((const float4*)(g_pr+(size_t)m*Dsz))[tid];
    const float4 c=((const float4*)(cb+(size_t)g_idx[m]*Dsz))[tid];
    float dx=c.x-f.x,dy=c.y-f.y,dz=c.z-f.z,dw=c.w-f.w;
    float v=dx*dx+dy*dy+dz*dz+dw*dw;
#pragma unroll
    for(int o=16;o;o>>=1) v+=__shfl_xor_sync(0xffffffffu,v,o);
    if((tid&31)==0) sw[tid>>5]=v;
    __syncthreads();
    if(tid==0) atomicAdd(&g_loss,(double)(sw[0]+sw[1]+sw[2]+sw[3]));
}

// ---------- gated stack scan: one warp per (b,d) ----------
__global__ __launch_bounds__(256) void scan_kernel(const float* __restrict__ cb) {
    __shared__ int sIdx[256]; __shared__ float sP[256],sO[256];
    const int b=blockIdx.x>>6, dg=blockIdx.x&63;
    const int warp=threadIdx.x>>5, lane=threadIdx.x&31;
    const int d=dg*8+warp;
    float st=0.f;
    for(int t0=0;t0<Lsz;t0+=256){
        __syncthreads();
        int ix=g_idx[b*Lsz+t0+threadIdx.x];
        sIdx[threadIdx.x]=ix; sP[threadIdx.x]=g_gp[ix]; sO[threadIdx.x]=g_go[ix];
        __syncthreads();
        for(int tt=0;tt<256;tt++){
            float val=cb[(size_t)sIdx[tt]*Dsz+d];
            float p=sP[tt],o=sO[tt];
            float sh=__shfl_down_sync(0xffffffffu,st,1);
            if(lane==31) sh=val;
            st=((1.f-p)*st+p*sh)*(1.f-o);
            if(lane==31) g_stk[((size_t)b*Lsz+t0+tt)*Dsz+d]=st;
        }
    }
}

// ---------- final: cr/ci, 2x layernorm, modulation, output ----------
__device__ __forceinline__ float blkRed(float v, float* s) {
#pragma unroll
    for(int o=16;o;o>>=1) v+=__shfl_xor_sync(0xffffffffu,v,o);
    if((threadIdx.x&31)==0) s[threadIdx.x>>5]=v;
    __syncthreads();
    v=s[0]+s[1]+s[2]+s[3];
    __syncthreads();
    return v;
}

__global__ void final_kernel(const float* __restrict__ cb,
                             const float* __restrict__ lng,
                             const float* __restrict__ lnb,
                             const float* __restrict__ mb,
                             float* __restrict__ out, long out_size) {
    __shared__ float sw[4];
    const int m=blockIdx.x, tid=threadIdx.x;
    const float* pr=g_pr+(size_t)m*Dsz;
    const float4 c4=((const float4*)(cb+(size_t)g_idx[m]*Dsz))[tid];
    const float4 f4=((const float4*)pr)[tid];
    const float4 s4=((const float4*)(g_stk+(size_t)m*Dsz))[tid];
    const float4 i4=((const float4*)(g_pi+(size_t)m*Dsz))[tid];
    float cr[4],ci[4];
    // zq_r_st = ar + (zq - ar), computed as reference does
    cr[0]=(f4.x+(c4.x-f4.x))+s4.x; cr[1]=(f4.y+(c4.y-f4.y))+s4.y;
    cr[2]=(f4.z+(c4.z-f4.z))+s4.z; cr[3]=(f4.w+(c4.w-f4.w))+s4.w;
    ci[0]=i4.x;ci[1]=i4.y;ci[2]=i4.z;ci[3]=i4.w;
    float sr=cr[0]+cr[1]+cr[2]+cr[3], si=ci[0]+ci[1]+ci[2]+ci[3];
    float mur=blkRed(sr,sw)*(1.f/Dsz);
    float mui=blkRed(si,sw)*(1.f/Dsz);
    float vr=0.f,vi=0.f;
#pragma unroll
    for(int k=0;k<4;k++){float a=cr[k]-mur,b=ci[k]-mui;vr+=a*a;vi+=b*b;}
    float varr=blkRed(vr,sw)*(1.f/Dsz);
    float vari=blkRed(vi,sw)*(1.f/Dsz);
    float rr=rsqrtf(varr+1e-5f), ri=rsqrtf(vari+1e-5f);
#pragma unroll
    for(int k=0;k<4;k++){
        int d=tid*4+k;
        float nr=(cr[k]-mur)*rr*lng[d]+lnb[d];
        float ni=(ci[k]-mui)*ri*lng[Dsz+d]+lnb[Dsz+d];
        float mag=sqrtf(nr*nr+ni*ni);
        float sc=fmaxf(mag+mb[d],0.f)/(mag+1e-6f);
        out[(size_t)m*Dsz+d]=nr*sc;
        out[OUTHALF+(size_t)m*Dsz+d]=ni*sc;
    }
    if(m==0&&tid==0)
        out[out_size-1]=(float)(1.25*g_loss/(double)((size_t)Msz*Dsz));
}

extern "C" void kernel_launch(void* const* d_in, const int* in_sizes, int n_in,
                              void* d_out, int out_size) {
    const int*   tokens=(const int*)  d_in[0];
    const float* embed =(const float*)d_in[2];
    const float* q_w=(const float*)d_in[3],  *q_b=(const float*)d_in[4];
    const float* k_w=(const float*)d_in[5],  *k_b=(const float*)d_in[6];
    const float* v_w=(const float*)d_in[7],  *v_b=(const float*)d_in[8];
    const float* o_w=(const float*)d_in[9],  *o_b=(const float*)d_in[10];
    const float* cb =(const float*)d_in[11];
    const float* gw =(const float*)d_in[12], *gb=(const float*)d_in[13];
    const float* lng=(const float*)d_in[14], *lnb=(const float*)d_in[15];
    const float* mb =(const float*)d_in[16];
    float* out=(float*)d_out;

    static bool attr_set=false;
    if(!attr_set){
        cudaFuncSetAttribute(attn_kernel,cudaFuncAttributeMaxDynamicSharedMemorySize,7*64*AP*4);
        attr_set=true;
    }
    prep_kernel<<<1,128>>>(cb,gw,gb);
    gather_kernel<<<Msz,128>>>(tokens,embed);
    proj_kernel<<<dim3(4,64,6),256>>>(q_w,q_b,k_w,k_b,v_w,v_b);
    attn_kernel<<<dim3(16,64),256,7*64*AP*4>>>();
    oproj_kernel<<<dim3(8,64),256>>>(o_w,o_b);
    dist_kernel<<<64,256>>>(cb);
    loss_kernel<<<Msz,128>>>(cb);
    scan_kernel<<<512,256>>>(cb);
    final_kernel<<<Msz,128>>>(cb,lng,lnb,mb,out,(long)out_size);
}